// round 2
// baseline (speedup 1.0000x reference)
#include <cuda_runtime.h>

#define NMAX 16384
#define KNN  16
#define CDIM 64
#define QPB  32     // queries per KNN block
#define GSPL 8      // threads (slices) per query
#define TILE 512    // candidates per smem tile
#define NODES_PER_BLOCK 16

// ---- scratch (no allocation allowed) ----
__device__ float4 g_pos4[NMAX];
__device__ int    g_knn[NMAX * KNN];
__device__ float  g_B[NMAX * CDIM];   // x @ W1b
__device__ float  g_C[NMAX * CDIM];   // x @ (W1a - W1b) + b1

// ============================================================
// Kernel 0: pack pos -> (x,y,z, |p|^2)
// ============================================================
__global__ void pack_pos_kernel(const float* __restrict__ pos, int n) {
    int i = blockIdx.x * blockDim.x + threadIdx.x;
    if (i < n) {
        float x = pos[i * 3 + 0];
        float y = pos[i * 3 + 1];
        float z = pos[i * 3 + 2];
        g_pos4[i] = make_float4(x, y, z, fmaf(x, x, fmaf(y, y, z * z)));
    }
}

// ============================================================
// Kernel 1: brute-force KNN (top-16 smallest squared distances)
// Layout: lane = query within block (32), warp = candidate slice (8).
// Every smem load in the scan is a warp-wide broadcast.
// ============================================================
__global__ __launch_bounds__(QPB * GSPL, 4)
void knn_kernel(int n) {
    __shared__ float4 tile[TILE];
    // transposed: lists[entry(0..127)][query(0..31)] -> conflict-free merge
    __shared__ unsigned long long lists[GSPL * KNN * QPB];

    const int tid  = threadIdx.x;
    const int w    = tid >> 5;   // slice index 0..7
    const int lane = tid & 31;   // query index within block
    const int q    = blockIdx.x * QPB + lane;

    const float4 qp = g_pos4[q];

    float bestd[KNN];
    int   besti[KNN];
#pragma unroll
    for (int r = 0; r < KNN; r++) { bestd[r] = 3.4e38f; besti[r] = 0; }
    float worst = 3.4e38f;
    int   wslot = 0;

    const int cbase = w * (TILE / GSPL);   // 64 candidates per slice per tile

    for (int t0 = 0; t0 < n; t0 += TILE) {
        // cooperative tile load (2 float4 per thread)
        for (int c = tid; c < TILE; c += QPB * GSPL)
            tile[c] = g_pos4[t0 + c];
        __syncthreads();

#pragma unroll 4
        for (int c = 0; c < TILE / GSPL; c++) {
            float4 p = tile[cbase + c];           // warp broadcast
            int   cj = t0 + cbase + c;
            float dot = fmaf(qp.x, p.x, fmaf(qp.y, p.y, qp.z * p.z));
            float dsq = qp.w + p.w - 2.0f * dot;  // same formula as reference
            if (dsq < worst && cj != q) {
                bestd[wslot] = fmaxf(dsq, 0.0f);  // keep u64 key ordering valid
                besti[wslot] = cj;
                worst = bestd[0]; wslot = 0;
#pragma unroll
                for (int r = 1; r < KNN; r++)
                    if (bestd[r] > worst) { worst = bestd[r]; wslot = r; }
            }
        }
        __syncthreads();
    }

    // publish local lists as packed (dist<<32 | idx)
#pragma unroll
    for (int r = 0; r < KNN; r++) {
        unsigned long long key =
            ((unsigned long long)__float_as_uint(bestd[r]) << 32) |
            (unsigned int)besti[r];
        lists[(w * KNN + r) * QPB + lane] = key;
    }
    __syncthreads();

    // merge: thread tid<32 selects 16 smallest of its query's 128 entries
    if (tid < QPB) {
        const int outbase = (blockIdx.x * QPB + tid) * KNN;
        for (int r = 0; r < KNN; r++) {
            unsigned long long m = ~0ULL;
            int mi = 0;
            for (int jj = 0; jj < GSPL * KNN; jj++) {
                unsigned long long v = lists[jj * QPB + tid];
                if (v < m) { m = v; mi = jj; }
            }
            lists[mi * QPB + tid] = ~0ULL;
            g_knn[outbase + r] = (int)(m & 0xffffffffu);
        }
    }
}

// ============================================================
// Kernel 2: B = x @ W1b ; C = x @ (W1a - W1b) + b1
// thread per (node, d); W1 columns coalesced across threads.
// ============================================================
__global__ void feat_kernel(const float* __restrict__ x,
                            const float* __restrict__ W1,
                            const float* __restrict__ b1, int n) {
    int t = blockIdx.x * blockDim.x + threadIdx.x;
    int nn = t >> 6;
    int d  = t & 63;
    if (nn >= n) return;
    const float* xr = x + nn * CDIM;
    float a = 0.0f, b = 0.0f;
#pragma unroll 8
    for (int c = 0; c < CDIM; c++) {
        float xv = xr[c];                       // warp broadcast, L1-hot
        a = fmaf(xv, W1[c * CDIM + d], a);        // W1a
        b = fmaf(xv, W1[(CDIM + c) * CDIM + d], b); // W1b
    }
    g_B[t] = b;
    g_C[t] = a - b + b1[d];
}

// ============================================================
// Kernel 3: per-edge relu + W2 matvec + max over K
// block = 64 threads (thread = output channel d), W2 column in registers,
// g double-buffered in smem read as broadcast float4.
// ============================================================
__global__ __launch_bounds__(64)
void edge_kernel(const float* __restrict__ W2,
                 const float* __restrict__ b2,
                 float* __restrict__ out, int n) {
    __shared__ float gs[2][CDIM];
    const int d = threadIdx.x;

    float w2r[CDIM];
#pragma unroll
    for (int e = 0; e < CDIM; e++)
        w2r[e] = W2[e * CDIM + d];   // coalesced across d
    const float b2d = b2[d];

    const int n0 = blockIdx.x * NODES_PER_BLOCK;
    for (int i = 0; i < NODES_PER_BLOCK; i++) {
        const int nn = n0 + i;
        const float cv = g_C[nn * CDIM + d];
        float m = -3.4e38f;
#pragma unroll
        for (int k = 0; k < KNN; k++) {
            int j = g_knn[nn * KNN + k];
            float gv = fmaxf(cv + g_B[j * CDIM + d], 0.0f);
            gs[k & 1][d] = gv;
            __syncthreads();
            const float4* gp = (const float4*)gs[k & 1];
            float acc = 0.0f;
#pragma unroll
            for (int e4 = 0; e4 < CDIM / 4; e4++) {
                float4 gq = gp[e4];               // 16B warp broadcast
                acc = fmaf(gq.x, w2r[4 * e4 + 0], acc);
                acc = fmaf(gq.y, w2r[4 * e4 + 1], acc);
                acc = fmaf(gq.z, w2r[4 * e4 + 2], acc);
                acc = fmaf(gq.w, w2r[4 * e4 + 3], acc);
            }
            m = fmaxf(m, acc);
        }
        out[nn * CDIM + d] = m + b2d;
        __syncthreads();   // protect gs buffers across node boundary
    }
}

// ============================================================
extern "C" void kernel_launch(void* const* d_in, const int* in_sizes, int n_in,
                              void* d_out, int out_size) {
    const float* x   = (const float*)d_in[0];
    const float* pos = (const float*)d_in[1];
    const float* W1  = (const float*)d_in[2];
    const float* b1  = (const float*)d_in[3];
    const float* W2  = (const float*)d_in[4];
    const float* b2  = (const float*)d_in[5];
    float* out = (float*)d_out;

    int n = in_sizes[1] / 3;
    if (n > NMAX) n = NMAX;

    pack_pos_kernel<<<(n + 255) / 256, 256>>>(pos, n);
    knn_kernel<<<n / QPB, QPB * GSPL>>>(n);
    feat_kernel<<<(n * CDIM + 255) / 256, 256>>>(x, W1, b1, n);
    edge_kernel<<<n / NODES_PER_BLOCK, CDIM>>>(W2, b2, out, n);
}